// round 7
// baseline (speedup 1.0000x reference)
#include <cuda_runtime.h>
#include <cuda_bf16.h>
#include <cstdint>

#define BDIM 4
#define SDIM 2048
#define IDIM 1024
#define DDIM 1024
#define NTOK (BDIM * SDIM)   // 8192

// ---------------------------------------------------------------------------
// Device scratch (allocation-free rule)
// ---------------------------------------------------------------------------
__device__ __align__(128) __nv_bfloat16 g_qh[(size_t)NTOK * IDIM];
__device__ __align__(128) __nv_bfloat16 g_ql[(size_t)NTOK * IDIM];
__device__ __align__(128) __nv_bfloat16 g_kh[(size_t)NTOK * IDIM];
__device__ __align__(128) __nv_bfloat16 g_kl[(size_t)NTOK * IDIM];
__device__ __align__(128) __nv_bfloat16 g_vh[(size_t)NTOK * IDIM];
__device__ __align__(128) __nv_bfloat16 g_vl[(size_t)NTOK * IDIM];
__device__ __align__(128) __nv_bfloat16 g_wqt_h[(size_t)DDIM * IDIM];
__device__ __align__(128) __nv_bfloat16 g_wqt_l[(size_t)DDIM * IDIM];
__device__ __align__(128) __nv_bfloat16 g_wkt_h[(size_t)DDIM * IDIM];
__device__ __align__(128) __nv_bfloat16 g_wkt_l[(size_t)DDIM * IDIM];
__device__ __align__(128) __nv_bfloat16 g_wvt_h[(size_t)DDIM * IDIM];
__device__ __align__(128) __nv_bfloat16 g_wvt_l[(size_t)DDIM * IDIM];
__device__ __align__(128) __nv_bfloat16 g_qph[(size_t)NTOK * DDIM];
__device__ __align__(128) __nv_bfloat16 g_qpl[(size_t)NTOK * DDIM];
__device__ __align__(128) __nv_bfloat16 g_kph[(size_t)NTOK * DDIM];
__device__ __align__(128) __nv_bfloat16 g_kpl[(size_t)NTOK * DDIM];
__device__ __align__(128) __nv_bfloat16 g_vpth[(size_t)DDIM * NTOK];  // [D, tokens]
__device__ __align__(128) __nv_bfloat16 g_vptl[(size_t)DDIM * NTOK];
__device__ __align__(128) float g_logits[(size_t)BDIM * SDIM * SDIM];
__device__ __align__(128) __nv_bfloat16 g_ah[(size_t)BDIM * SDIM * SDIM];
__device__ __align__(128) __nv_bfloat16 g_al[(size_t)BDIM * SDIM * SDIM];

// ---------------------------------------------------------------------------
// PTX helpers
// ---------------------------------------------------------------------------
__device__ __forceinline__ uint32_t smem_u32(const void* p) {
    uint32_t a;
    asm("{ .reg .u64 t; cvta.to.shared.u64 t, %1; cvt.u32.u64 %0, t; }"
        : "=r"(a) : "l"(p));
    return a;
}

__device__ __forceinline__ void cp16(uint32_t d, const void* g) {
    asm volatile("cp.async.cg.shared.global [%0], [%1], 16;" :: "r"(d), "l"(g) : "memory");
}
#define CP_COMMIT() asm volatile("cp.async.commit_group;" ::: "memory")
#define CP_WAIT1()  asm volatile("cp.async.wait_group 1;" ::: "memory")

__device__ __forceinline__ void ldsm4(uint32_t* r, uint32_t addr) {
    asm volatile("ldmatrix.sync.aligned.m8n8.x4.shared.b16 {%0,%1,%2,%3}, [%4];"
        : "=r"(r[0]), "=r"(r[1]), "=r"(r[2]), "=r"(r[3]) : "r"(addr));
}

// mma.sync m16n8k16 bf16 -> fp32 accumulate
__device__ __forceinline__ void mma_bf16(float* d, const uint32_t* a,
                                         uint32_t b0, uint32_t b1) {
    asm volatile(
        "mma.sync.aligned.m16n8k16.row.col.f32.bf16.bf16.f32 "
        "{%0,%1,%2,%3}, {%4,%5,%6,%7}, {%8,%9}, {%0,%1,%2,%3};"
        : "+f"(d[0]), "+f"(d[1]), "+f"(d[2]), "+f"(d[3])
        : "r"(a[0]), "r"(a[1]), "r"(a[2]), "r"(a[3]), "r"(b0), "r"(b1));
}

// CTA tile 128(M) x 256(N), K-tile 32. SMEM rows: A 128, B 256, pitch 80B.
#define KT 32
#define ROWB 80
#define A_BYTES (128 * ROWB)            // 10240
#define B_BYTES (256 * ROWB)            // 20480
#define OFF_AH 0
#define OFF_AL A_BYTES
#define OFF_BH (2 * A_BYTES)
#define OFF_BL (2 * A_BYTES + B_BYTES)
#define STG_BYTES (2 * A_BYTES + 2 * B_BYTES)   // 61440
#define NSTAGE 3
#define SMEM_TOTAL (NSTAGE * STG_BYTES)         // 184320

#define NTHREADS 512

// ROWS*4 chunk-loads of 16B; 512 threads
template <int ITERS>
__device__ __forceinline__ void load_arr(const __nv_bfloat16* __restrict__ G,
                                         int ldg, int kt, uint32_t dst, int tid) {
#pragma unroll
    for (int i = 0; i < ITERS; i++) {
        int idx = tid + i * NTHREADS;
        int row = idx >> 2;
        int c = idx & 3;
        cp16(dst + row * ROWB + c * 16, (const void*)(G + (size_t)row * ldg + kt + c * 8));
    }
}

// ---------------------------------------------------------------------------
// Shared mainloop: D[128,256] += A[128,K] * B[256,K]^T (NT, hi/lo 3-product).
// 16 warps (4 m x 4 n), warp tile 32x64.
// ---------------------------------------------------------------------------
__device__ __forceinline__ void gemm_mainloop(
    const __nv_bfloat16* __restrict__ Ahb, const __nv_bfloat16* __restrict__ Alb,
    const __nv_bfloat16* __restrict__ Bhb, const __nv_bfloat16* __restrict__ Blb,
    int K, int lda, int ldb,
    uint32_t sbase, int tid, int wm, int wn, int lane,
    float d[2][8][4])
{
    const int w8 = lane & 7, j8 = lane >> 3;
    int aoff[2], boff[4];
#pragma unroll
    for (int mf = 0; mf < 2; mf++)
        aoff[mf] = (wm * 32 + mf * 16 + w8 + 8 * (j8 & 1)) * ROWB + (j8 >> 1) * 16;
#pragma unroll
    for (int g = 0; g < 4; g++)
        boff[g] = (wn * 64 + g * 16 + w8 + 8 * (j8 >> 1)) * ROWB + (j8 & 1) * 16;

    const int T = K / KT;

    // preload stages 0,1
#pragma unroll
    for (int p = 0; p < 2; p++) {
        uint32_t b = sbase + p * STG_BYTES;
        load_arr<1>(Ahb, lda, p * KT, b + OFF_AH, tid);
        load_arr<1>(Alb, lda, p * KT, b + OFF_AL, tid);
        load_arr<2>(Bhb, ldb, p * KT, b + OFF_BH, tid);
        load_arr<2>(Blb, ldb, p * KT, b + OFF_BL, tid);
        CP_COMMIT();
    }

    int stg = 0;
    for (int t = 0; t < T; t++) {
        CP_WAIT1();            // stage t complete
        __syncthreads();

        // prefetch stage t+2 into slot (stg+2)%3 (consumed at t-1; barrier protects)
        if (t + 2 < T) {
            int ps = stg + 2; if (ps >= NSTAGE) ps -= NSTAGE;
            uint32_t pb = sbase + ps * STG_BYTES;
            const int kt = (t + 2) * KT;
            load_arr<1>(Ahb, lda, kt, pb + OFF_AH, tid);
            load_arr<1>(Alb, lda, kt, pb + OFF_AL, tid);
            load_arr<2>(Bhb, ldb, kt, pb + OFF_BH, tid);
            load_arr<2>(Blb, ldb, kt, pb + OFF_BL, tid);
        }
        CP_COMMIT();

        const uint32_t sb = sbase + stg * STG_BYTES;
        const uint32_t sAh = sb + OFF_AH;
        const uint32_t sAl = sb + OFF_AL;
        const uint32_t sBh = sb + OFF_BH;
        const uint32_t sBl = sb + OFF_BL;

#pragma unroll
        for (int ks = 0; ks < 2; ks++) {
            const int kb = ks * 32;   // 16 bf16 = 32 bytes
            uint32_t ah[2][4], al[2][4];
            ldsm4(ah[0], sAh + aoff[0] + kb);
            ldsm4(ah[1], sAh + aoff[1] + kb);
            ldsm4(al[0], sAl + aoff[0] + kb);
            ldsm4(al[1], sAl + aoff[1] + kb);
#pragma unroll
            for (int g = 0; g < 4; g++) {
                uint32_t bh[4], bl[4];
                ldsm4(bh, sBh + boff[g] + kb);
                ldsm4(bl, sBl + boff[g] + kb);
#pragma unroll
                for (int sub = 0; sub < 2; sub++) {
                    const int nf = g * 2 + sub;
                    const uint32_t bh0 = bh[sub * 2], bh1 = bh[sub * 2 + 1];
                    const uint32_t bl0 = bl[sub * 2], bl1 = bl[sub * 2 + 1];
                    mma_bf16(d[0][nf], ah[0], bh0, bh1);
                    mma_bf16(d[1][nf], ah[1], bh0, bh1);
                    mma_bf16(d[0][nf], ah[0], bl0, bl1);
                    mma_bf16(d[1][nf], ah[1], bl0, bl1);
                    mma_bf16(d[0][nf], al[0], bh0, bh1);
                    mma_bf16(d[1][nf], al[1], bh0, bh1);
                }
            }
        }

        stg++; if (stg >= NSTAGE) stg = 0;
    }
}

// ---------------------------------------------------------------------------
// Merged QKV projection GEMM. blockIdx.z in {0,1,2} selects {Q,K,V}.
// ---------------------------------------------------------------------------
__global__ void __launch_bounds__(NTHREADS)
proj_gemm(const __nv_bfloat16* __restrict__ qh, const __nv_bfloat16* __restrict__ ql,
          const __nv_bfloat16* __restrict__ kh, const __nv_bfloat16* __restrict__ kl,
          const __nv_bfloat16* __restrict__ vh, const __nv_bfloat16* __restrict__ vl,
          const __nv_bfloat16* __restrict__ wqh, const __nv_bfloat16* __restrict__ wql,
          const __nv_bfloat16* __restrict__ wkh, const __nv_bfloat16* __restrict__ wkl,
          const __nv_bfloat16* __restrict__ wvh, const __nv_bfloat16* __restrict__ wvl,
          const float* __restrict__ bq, const float* __restrict__ bk,
          const float* __restrict__ bv,
          __nv_bfloat16* __restrict__ qph, __nv_bfloat16* __restrict__ qpl,
          __nv_bfloat16* __restrict__ kph, __nv_bfloat16* __restrict__ kpl,
          __nv_bfloat16* __restrict__ vpth, __nv_bfloat16* __restrict__ vptl)
{
    extern __shared__ char smem[];
    const uint32_t sbase = smem_u32(smem);
    const int tid = threadIdx.x;
    const int wid = tid >> 5, lane = tid & 31;
    const int wm = wid & 3, wn = wid >> 2;
    const int mBase = blockIdx.y * 128;
    const int nBase = blockIdx.x * 256;
    const int z = blockIdx.z;

    const __nv_bfloat16* Ah = (z == 0) ? qh : (z == 1) ? kh : vh;
    const __nv_bfloat16* Al = (z == 0) ? ql : (z == 1) ? kl : vl;
    const __nv_bfloat16* Bh = (z == 0) ? wqh : (z == 1) ? wkh : wvh;
    const __nv_bfloat16* Bl = (z == 0) ? wql : (z == 1) ? wkl : wvl;
    const float* bias = (z == 0) ? bq : (z == 1) ? bk : bv;
    __nv_bfloat16* Ch = (z == 0) ? qph : (z == 1) ? kph : vpth;
    __nv_bfloat16* Cl = (z == 0) ? qpl : (z == 1) ? kpl : vptl;

    float d[2][8][4];
#pragma unroll
    for (int i = 0; i < 2; i++)
#pragma unroll
        for (int j = 0; j < 8; j++)
#pragma unroll
            for (int e = 0; e < 4; e++) d[i][j][e] = 0.f;

    gemm_mainloop(Ah + (size_t)mBase * IDIM, Al + (size_t)mBase * IDIM,
                  Bh + (size_t)nBase * IDIM, Bl + (size_t)nBase * IDIM,
                  IDIM, IDIM, IDIM, sbase, tid, wm, wn, lane, d);

    const int row0 = mBase + wm * 32 + (lane >> 2);
    const int col0 = nBase + wn * 64 + (lane & 3) * 2;

#pragma unroll
    for (int mf = 0; mf < 2; mf++) {
#pragma unroll
        for (int nf = 0; nf < 8; nf++) {
            const int r = row0 + mf * 16;
            const int c = col0 + nf * 8;
            const float* dd = d[mf][nf];
            const float b0v = bias[c], b1v = bias[c + 1];
#pragma unroll
            for (int h = 0; h < 2; h++) {
                float v0 = dd[h * 2 + 0] + b0v;
                float v1 = dd[h * 2 + 1] + b1v;
                __nv_bfloat16 h0 = __float2bfloat16(v0);
                __nv_bfloat16 h1 = __float2bfloat16(v1);
                __nv_bfloat16 l0 = __float2bfloat16(v0 - __bfloat162float(h0));
                __nv_bfloat16 l1 = __float2bfloat16(v1 - __bfloat162float(h1));
                int rr = r + h * 8;
                if (z != 2) {
                    size_t o = (size_t)rr * DDIM + c;
                    *(__nv_bfloat162*)(Ch + o) = __nv_bfloat162(h0, h1);
                    *(__nv_bfloat162*)(Cl + o) = __nv_bfloat162(l0, l1);
                } else {
                    Ch[(size_t)c * NTOK + rr] = h0;
                    Cl[(size_t)c * NTOK + rr] = l0;
                    Ch[(size_t)(c + 1) * NTOK + rr] = h1;
                    Cl[(size_t)(c + 1) * NTOK + rr] = l1;
                }
            }
        }
    }
}

// ---------------------------------------------------------------------------
// Generic NT GEMM with fp32 output (logits & AV), batched via strides.
// ---------------------------------------------------------------------------
__global__ void __launch_bounds__(NTHREADS)
hmma_gemm_f32(const __nv_bfloat16* __restrict__ Ah, const __nv_bfloat16* __restrict__ Al,
              const __nv_bfloat16* __restrict__ Bh, const __nv_bfloat16* __restrict__ Bl,
              float* __restrict__ Cf,
              int K, int lda, int ldb, int ldc,
              size_t sA, size_t sB, size_t sC)
{
    extern __shared__ char smem[];
    const uint32_t sbase = smem_u32(smem);
    const int tid = threadIdx.x;
    const int wid = tid >> 5, lane = tid & 31;
    const int wm = wid & 3, wn = wid >> 2;
    const int mBase = blockIdx.y * 128;
    const int nBase = blockIdx.x * 256;
    const int z = blockIdx.z;

    float d[2][8][4];
#pragma unroll
    for (int i = 0; i < 2; i++)
#pragma unroll
        for (int j = 0; j < 8; j++)
#pragma unroll
            for (int e = 0; e < 4; e++) d[i][j][e] = 0.f;

    gemm_mainloop(Ah + z * sA + (size_t)mBase * lda, Al + z * sA + (size_t)mBase * lda,
                  Bh + z * sB + (size_t)nBase * ldb, Bl + z * sB + (size_t)nBase * ldb,
                  K, lda, ldb, sbase, tid, wm, wn, lane, d);

    const int row0 = mBase + wm * 32 + (lane >> 2);
    const int col0 = nBase + wn * 64 + (lane & 3) * 2;
    float* Cp = Cf + z * sC;

#pragma unroll
    for (int mf = 0; mf < 2; mf++) {
#pragma unroll
        for (int nf = 0; nf < 8; nf++) {
            const int r = row0 + mf * 16;
            const int c = col0 + nf * 8;
            const float* dd = d[mf][nf];
            *(float2*)(Cp + (size_t)r * ldc + c) = make_float2(dd[0], dd[1]);
            *(float2*)(Cp + (size_t)(r + 8) * ldc + c) = make_float2(dd[2], dd[3]);
        }
    }
}

// ---------------------------------------------------------------------------
// fp32 -> (hi, lo) bf16 split; grid.y selects among 3 tensors
// ---------------------------------------------------------------------------
__global__ void __launch_bounds__(256)
split_f32_3(const float4* __restrict__ x0, __nv_bfloat16* __restrict__ h0p, __nv_bfloat16* __restrict__ l0p,
            const float4* __restrict__ x1, __nv_bfloat16* __restrict__ h1p, __nv_bfloat16* __restrict__ l1p,
            const float4* __restrict__ x2, __nv_bfloat16* __restrict__ h2p, __nv_bfloat16* __restrict__ l2p,
            int n4)
{
    int i = blockIdx.x * 256 + threadIdx.x;
    if (i >= n4) return;
    int s = blockIdx.y;
    const float4* x = (s == 0) ? x0 : (s == 1) ? x1 : x2;
    __nv_bfloat16* hi = (s == 0) ? h0p : (s == 1) ? h1p : h2p;
    __nv_bfloat16* lo = (s == 0) ? l0p : (s == 1) ? l1p : l2p;

    float4 v = x[i];
    float vv[4] = {v.x, v.y, v.z, v.w};
    __nv_bfloat162 h2[2], l2[2];
#pragma unroll
    for (int j = 0; j < 4; j++) {
        __nv_bfloat16 h = __float2bfloat16(vv[j]);
        __nv_bfloat16 l = __float2bfloat16(vv[j] - __bfloat162float(h));
        ((__nv_bfloat16*)h2)[j] = h;
        ((__nv_bfloat16*)l2)[j] = l;
    }
    ((__nv_bfloat162*)hi)[i * 2]     = h2[0];
    ((__nv_bfloat162*)hi)[i * 2 + 1] = h2[1];
    ((__nv_bfloat162*)lo)[i * 2]     = l2[0];
    ((__nv_bfloat162*)lo)[i * 2 + 1] = l2[1];
}

// Merged W[K,N] fp32 -> WT hi/lo [N,K] bf16 for all 3 weights (grid.z)
__global__ void __launch_bounds__(256)
transpose_split_3(const float* __restrict__ W0, __nv_bfloat16* __restrict__ T0h, __nv_bfloat16* __restrict__ T0l,
                  const float* __restrict__ W1, __nv_bfloat16* __restrict__ T1h, __nv_bfloat16* __restrict__ T1l,
                  const float* __restrict__ W2, __nv_bfloat16* __restrict__ T2h, __nv_bfloat16* __restrict__ T2l,
                  int rows, int cols)
{
    __shared__ float tile[32][33];
    int s = blockIdx.z;
    const float* W = (s == 0) ? W0 : (s == 1) ? W1 : W2;
    __nv_bfloat16* Th = (s == 0) ? T0h : (s == 1) ? T1h : T2h;
    __nv_bfloat16* Tl = (s == 0) ? T0l : (s == 1) ? T1l : T2l;

    int bx = blockIdx.x * 32;  // n
    int by = blockIdx.y * 32;  // k
    int tx = threadIdx.x & 31;
    int ty = threadIdx.x >> 5; // 0..7
#pragma unroll
    for (int i = ty; i < 32; i += 8)
        tile[i][tx] = W[(size_t)(by + i) * cols + bx + tx];
    __syncthreads();
#pragma unroll
    for (int i = ty; i < 32; i += 8) {
        float v = tile[tx][i];  // = W[by+tx][bx+i]
        __nv_bfloat16 h = __float2bfloat16(v);
        __nv_bfloat16 l = __float2bfloat16(v - __bfloat162float(h));
        size_t o = (size_t)(bx + i) * rows + by + tx;
        Th[o] = h;
        Tl[o] = l;
    }
}

// ---------------------------------------------------------------------------
// scale+mask+softmax, fp32 logits in -> bf16 hi/lo attn out
// ---------------------------------------------------------------------------
__global__ void __launch_bounds__(256)
softmax_split(const float* __restrict__ logits, const float* __restrict__ mask,
              __nv_bfloat16* __restrict__ ah, __nv_bfloat16* __restrict__ al,
              float scale)
{
    __shared__ float red[8];
    __shared__ float bval;

    size_t row = blockIdx.x;
    int q = (int)(row & (SDIM - 1));
    const float* rp = logits + row * (size_t)SDIM;
    const float* mp = mask + (size_t)q * SDIM;
    int t = threadIdx.x;

    float4 a = ((const float4*)rp)[t];
    float4 b = ((const float4*)rp)[t + 256];
    float4 ma = ((const float4*)mp)[t];
    float4 mb = ((const float4*)mp)[t + 256];
    float x[8];
    x[0] = fmaf(a.x, scale, ma.x); x[1] = fmaf(a.y, scale, ma.y);
    x[2] = fmaf(a.z, scale, ma.z); x[3] = fmaf(a.w, scale, ma.w);
    x[4] = fmaf(b.x, scale, mb.x); x[5] = fmaf(b.y, scale, mb.y);
    x[6] = fmaf(b.z, scale, mb.z); x[7] = fmaf(b.w, scale, mb.w);

    float mx = x[0];
#pragma unroll
    for (int i = 1; i < 8; i++) mx = fmaxf(mx, x[i]);
#pragma unroll
    for (int o = 16; o; o >>= 1) mx = fmaxf(mx, __shfl_xor_sync(0xffffffffu, mx, o));
    if ((t & 31) == 0) red[t >> 5] = mx;
    __syncthreads();
    if (t == 0) {
        float m = red[0];
#pragma unroll
        for (int i = 1; i < 8; i++) m = fmaxf(m, red[i]);
        bval = m;
    }
    __syncthreads();
    mx = bval;

    float s = 0.f;
#pragma unroll
    for (int i = 0; i < 8; i++) { x[i] = __expf(x[i] - mx); s += x[i]; }
#pragma unroll
    for (int o = 16; o; o >>= 1) s += __shfl_xor_sync(0xffffffffu, s, o);
    if ((t & 31) == 0) red[t >> 5] = s;
    __syncthreads();
    if (t == 0) {
        float ss = 0.f;
#pragma unroll
        for (int i = 0; i < 8; i++) ss += red[i];
        bval = 1.f / ss;
    }
    __syncthreads();
    float inv = bval;

    __nv_bfloat162* ah2 = (__nv_bfloat162*)(ah + row * (size_t)SDIM);
    __nv_bfloat162* al2 = (__nv_bfloat162*)(al + row * (size_t)SDIM);
#pragma unroll
    for (int half = 0; half < 2; half++) {
#pragma unroll
        for (int p = 0; p < 2; p++) {
            float p0 = x[half * 4 + p * 2 + 0] * inv;
            float p1 = x[half * 4 + p * 2 + 1] * inv;
            __nv_bfloat16 h0 = __float2bfloat16(p0);
            __nv_bfloat16 h1 = __float2bfloat16(p1);
            __nv_bfloat16 l0 = __float2bfloat16(p0 - __bfloat162float(h0));
            __nv_bfloat16 l1 = __float2bfloat16(p1 - __bfloat162float(h1));
            int idx = half * 512 + t * 2 + p;
            ah2[idx] = __nv_bfloat162(h0, h1);
            al2[idx] = __nv_bfloat162(l0, l1);
        }
    }
}

// ---------------------------------------------------------------------------
extern "C" void kernel_launch(void* const* d_in, const int* in_sizes, int n_in,
                              void* d_out, int out_size)
{
    const float* q    = (const float*)d_in[0];
    const float* k    = (const float*)d_in[1];
    const float* v    = (const float*)d_in[2];
    const float* mask = (const float*)d_in[3];
    const float* wq   = (const float*)d_in[4];
    const float* bq   = (const float*)d_in[5];
    const float* wk   = (const float*)d_in[6];
    const float* bk   = (const float*)d_in[7];
    const float* wv   = (const float*)d_in[8];
    const float* bv   = (const float*)d_in[9];
    float* out = (float*)d_out;

#define SYM(p, s) do { void* _t; cudaGetSymbolAddress(&_t, s); p = (decltype(p))_t; } while (0)
    __nv_bfloat16 *qh, *ql, *kh, *kl, *vh, *vl;
    __nv_bfloat16 *wqth, *wqtl, *wkth, *wktl, *wvth, *wvtl;
    __nv_bfloat16 *qph, *qpl, *kph, *kpl, *vpth, *vptl, *ah, *al;
    float* lg;
    SYM(qh, g_qh); SYM(ql, g_ql); SYM(kh, g_kh); SYM(kl, g_kl);
    SYM(vh, g_vh); SYM(vl, g_vl);
    SYM(wqth, g_wqt_h); SYM(wqtl, g_wqt_l);
    SYM(wkth, g_wkt_h); SYM(wktl, g_wkt_l);
    SYM(wvth, g_wvt_h); SYM(wvtl, g_wvt_l);
    SYM(qph, g_qph); SYM(qpl, g_qpl); SYM(kph, g_kph); SYM(kpl, g_kpl);
    SYM(vpth, g_vpth); SYM(vptl, g_vptl);
    SYM(ah, g_ah); SYM(al, g_al);
    SYM(lg, g_logits);
#undef SYM

    cudaFuncSetAttribute(proj_gemm, cudaFuncAttributeMaxDynamicSharedMemorySize, SMEM_TOTAL);
    cudaFuncSetAttribute(hmma_gemm_f32, cudaFuncAttributeMaxDynamicSharedMemorySize, SMEM_TOTAL);

    const int n4 = NTOK * IDIM / 4;

    // 1: merged hi/lo split of q, k, v
    split_f32_3<<<dim3(n4 / 256, 3), 256>>>((const float4*)q, qh, ql,
                                            (const float4*)k, kh, kl,
                                            (const float4*)v, vh, vl, n4);
    // 2: merged weight transpose+split
    transpose_split_3<<<dim3(IDIM / 32, IDIM / 32, 3), 256>>>(
        wq, wqth, wqtl, wk, wkth, wktl, wv, wvth, wvtl, IDIM, DDIM);

    // 3: merged QKV projections (z selects operand set; z=2 writes vp^T)
    dim3 gp(DDIM / 256, NTOK / 128, 3);
    proj_gemm<<<gp, NTHREADS, SMEM_TOTAL>>>(qh, ql, kh, kl, vh, vl,
                                            wqth, wqtl, wkth, wktl, wvth, wvtl,
                                            bq, bk, bv,
                                            qph, qpl, kph, kpl, vpth, vptl);

    // 4: logits = qp @ kp^T (batched over B)   <- ncu profiles this launch
    dim3 gl(SDIM / 256, SDIM / 128, BDIM);
    hmma_gemm_f32<<<gl, NTHREADS, SMEM_TOTAL>>>(qph, qpl, kph, kpl, lg,
                                                DDIM, DDIM, DDIM, SDIM,
                                                (size_t)SDIM * DDIM, (size_t)SDIM * DDIM,
                                                (size_t)SDIM * SDIM);

    // 5: softmax -> attn hi/lo
    softmax_split<<<BDIM * SDIM, 256>>>(lg, mask, ah, al, 0.03125f);

    // 6: out = attn @ vp (B operand = vp^T, batch offset = column shift)
    dim3 ga(DDIM / 256, SDIM / 128, BDIM);
    hmma_gemm_f32<<<ga, NTHREADS, SMEM_TOTAL>>>(ah, al, vpth, vptl, out,
                                                SDIM, SDIM, NTOK, DDIM,
                                                (size_t)SDIM * SDIM, (size_t)SDIM,
                                                (size_t)SDIM * DDIM);
}

// round 8
// speedup vs baseline: 1.1010x; 1.1010x over previous
#include <cuda_runtime.h>
#include <cuda_bf16.h>
#include <cstdint>

#define BDIM 4
#define SDIM 2048
#define IDIM 1024
#define DDIM 1024
#define NTOK (BDIM * SDIM)   // 8192

// ---------------------------------------------------------------------------
// Device scratch (allocation-free rule)
// ---------------------------------------------------------------------------
__device__ __align__(128) __nv_bfloat16 g_qh[(size_t)NTOK * IDIM];
__device__ __align__(128) __nv_bfloat16 g_ql[(size_t)NTOK * IDIM];
__device__ __align__(128) __nv_bfloat16 g_kh[(size_t)NTOK * IDIM];
__device__ __align__(128) __nv_bfloat16 g_kl[(size_t)NTOK * IDIM];
__device__ __align__(128) __nv_bfloat16 g_vh[(size_t)NTOK * IDIM];
__device__ __align__(128) __nv_bfloat16 g_vl[(size_t)NTOK * IDIM];
__device__ __align__(128) __nv_bfloat16 g_wqt_h[(size_t)DDIM * IDIM];
__device__ __align__(128) __nv_bfloat16 g_wqt_l[(size_t)DDIM * IDIM];
__device__ __align__(128) __nv_bfloat16 g_wkt_h[(size_t)DDIM * IDIM];
__device__ __align__(128) __nv_bfloat16 g_wkt_l[(size_t)DDIM * IDIM];
__device__ __align__(128) __nv_bfloat16 g_wvt_h[(size_t)DDIM * IDIM];
__device__ __align__(128) __nv_bfloat16 g_wvt_l[(size_t)DDIM * IDIM];
__device__ __align__(128) __nv_bfloat16 g_qph[(size_t)NTOK * DDIM];
__device__ __align__(128) __nv_bfloat16 g_qpl[(size_t)NTOK * DDIM];
__device__ __align__(128) __nv_bfloat16 g_kph[(size_t)NTOK * DDIM];
__device__ __align__(128) __nv_bfloat16 g_kpl[(size_t)NTOK * DDIM];
__device__ __align__(128) __nv_bfloat16 g_vpth[(size_t)DDIM * NTOK];  // [D, tokens]
__device__ __align__(128) __nv_bfloat16 g_vptl[(size_t)DDIM * NTOK];
__device__ __align__(128) float g_logits[(size_t)BDIM * SDIM * SDIM];
__device__ __align__(128) __nv_bfloat16 g_ah[(size_t)BDIM * SDIM * SDIM];
__device__ __align__(128) __nv_bfloat16 g_al[(size_t)BDIM * SDIM * SDIM];

// ---------------------------------------------------------------------------
// PTX helpers
// ---------------------------------------------------------------------------
__device__ __forceinline__ uint32_t smem_u32(const void* p) {
    uint32_t a;
    asm("{ .reg .u64 t; cvta.to.shared.u64 t, %1; cvt.u32.u64 %0, t; }"
        : "=r"(a) : "l"(p));
    return a;
}

__device__ __forceinline__ void cp16(uint32_t d, const void* g) {
    asm volatile("cp.async.cg.shared.global [%0], [%1], 16;" :: "r"(d), "l"(g) : "memory");
}
#define CP_COMMIT() asm volatile("cp.async.commit_group;" ::: "memory")
#define CP_WAIT1()  asm volatile("cp.async.wait_group 1;" ::: "memory")

__device__ __forceinline__ void ldsm4(uint32_t* r, uint32_t addr) {
    asm volatile("ldmatrix.sync.aligned.m8n8.x4.shared.b16 {%0,%1,%2,%3}, [%4];"
        : "=r"(r[0]), "=r"(r[1]), "=r"(r[2]), "=r"(r[3]) : "r"(addr));
}

// mma.sync m16n8k16 bf16 -> fp32 accumulate
__device__ __forceinline__ void mma_bf16(float* d, const uint32_t* a,
                                         uint32_t b0, uint32_t b1) {
    asm volatile(
        "mma.sync.aligned.m16n8k16.row.col.f32.bf16.bf16.f32 "
        "{%0,%1,%2,%3}, {%4,%5,%6,%7}, {%8,%9}, {%0,%1,%2,%3};"
        : "+f"(d[0]), "+f"(d[1]), "+f"(d[2]), "+f"(d[3])
        : "r"(a[0]), "r"(a[1]), "r"(a[2]), "r"(a[3]), "r"(b0), "r"(b1));
}

// SMEM stage: 4 arrays of 128 rows x 144B pitch (128B = 64 bf16, K-tile 64)
#define KT 64
#define ROWB 144
#define ARR_BYTES (128 * ROWB)          // 18432
#define OFF_AH 0
#define OFF_AL ARR_BYTES
#define OFF_BH (2 * ARR_BYTES)
#define OFF_BL (3 * ARR_BYTES)
#define STG_BYTES (4 * ARR_BYTES)       // 73728
#define NSTAGE 3
#define SMEM_TOTAL (NSTAGE * STG_BYTES) // 221184

#define NTHREADS 512

__device__ __forceinline__ void load_arr(const __nv_bfloat16* __restrict__ G,
                                         int ldg, int kt, uint32_t dst, int tid) {
#pragma unroll
    for (int i = 0; i < 2; i++) {
        int idx = tid + i * NTHREADS;
        int row = idx >> 3;
        int c = idx & 7;
        cp16(dst + row * ROWB + c * 16, (const void*)(G + (size_t)row * ldg + kt + c * 8));
    }
}

// Fragment set for one k-step (warp tile 32x32)
struct Frags {
    uint32_t ah[2][4], al[2][4], bh[2][4], bl[2][4];
};

__device__ __forceinline__ void ld_frags(Frags& f, uint32_t sAh, uint32_t sAl,
                                         uint32_t sBh, uint32_t sBl, int kb,
                                         const int aoff[2], const int boff[2]) {
    ldsm4(f.ah[0], sAh + aoff[0] + kb);
    ldsm4(f.ah[1], sAh + aoff[1] + kb);
    ldsm4(f.bh[0], sBh + boff[0] + kb);
    ldsm4(f.bh[1], sBh + boff[1] + kb);
    ldsm4(f.al[0], sAl + aoff[0] + kb);
    ldsm4(f.al[1], sAl + aoff[1] + kb);
    ldsm4(f.bl[0], sBl + boff[0] + kb);
    ldsm4(f.bl[1], sBl + boff[1] + kb);
}

__device__ __forceinline__ void do_mmas(const Frags& f, float d[2][4][4]) {
#pragma unroll
    for (int g = 0; g < 2; g++) {
#pragma unroll
        for (int sub = 0; sub < 2; sub++) {
            const int nf = g * 2 + sub;
            const uint32_t bh0 = f.bh[g][sub * 2], bh1 = f.bh[g][sub * 2 + 1];
            const uint32_t bl0 = f.bl[g][sub * 2], bl1 = f.bl[g][sub * 2 + 1];
            mma_bf16(d[0][nf], f.ah[0], bh0, bh1);
            mma_bf16(d[1][nf], f.ah[1], bh0, bh1);
            mma_bf16(d[0][nf], f.ah[0], bl0, bl1);
            mma_bf16(d[1][nf], f.ah[1], bl0, bl1);
            mma_bf16(d[0][nf], f.al[0], bh0, bh1);
            mma_bf16(d[1][nf], f.al[1], bh0, bh1);
        }
    }
}

// ---------------------------------------------------------------------------
// Shared mainloop: D[128,128] += A[128,K] * B[128,K]^T (NT, hi/lo 3-product).
// 16 warps (4 m x 4 n), warp tile 32x32; register-double-buffered fragments.
// ---------------------------------------------------------------------------
__device__ __forceinline__ void gemm_mainloop(
    const __nv_bfloat16* __restrict__ Ahb, const __nv_bfloat16* __restrict__ Alb,
    const __nv_bfloat16* __restrict__ Bhb, const __nv_bfloat16* __restrict__ Blb,
    int K, int lda, int ldb,
    uint32_t sbase, int tid, int wm, int wn, int lane,
    float d[2][4][4])
{
    const int w8 = lane & 7, j8 = lane >> 3;
    int aoff[2], boff[2];
#pragma unroll
    for (int mf = 0; mf < 2; mf++)
        aoff[mf] = (wm * 32 + mf * 16 + w8 + 8 * (j8 & 1)) * ROWB + (j8 >> 1) * 16;
#pragma unroll
    for (int g = 0; g < 2; g++)
        boff[g] = (wn * 32 + g * 16 + w8 + 8 * (j8 >> 1)) * ROWB + (j8 & 1) * 16;

    const int T = K / KT;

    // preload stages 0,1
#pragma unroll
    for (int p = 0; p < 2; p++) {
        uint32_t b = sbase + p * STG_BYTES;
        load_arr(Ahb, lda, p * KT, b + OFF_AH, tid);
        load_arr(Alb, lda, p * KT, b + OFF_AL, tid);
        load_arr(Bhb, ldb, p * KT, b + OFF_BH, tid);
        load_arr(Blb, ldb, p * KT, b + OFF_BL, tid);
        CP_COMMIT();
    }

    Frags fr[2];
    int stg = 0;
    for (int t = 0; t < T; t++) {
        CP_WAIT1();            // stage t complete
        __syncthreads();

        // prefetch stage t+2 into slot (stg+2)%3 (consumed at t-1; barrier protects)
        if (t + 2 < T) {
            int ps = stg + 2; if (ps >= NSTAGE) ps -= NSTAGE;
            uint32_t pb = sbase + ps * STG_BYTES;
            const int kt = (t + 2) * KT;
            load_arr(Ahb, lda, kt, pb + OFF_AH, tid);
            load_arr(Alb, lda, kt, pb + OFF_AL, tid);
            load_arr(Bhb, ldb, kt, pb + OFF_BH, tid);
            load_arr(Blb, ldb, kt, pb + OFF_BL, tid);
        }
        CP_COMMIT();

        const uint32_t sb = sbase + stg * STG_BYTES;
        const uint32_t sAh = sb + OFF_AH;
        const uint32_t sAl = sb + OFF_AL;
        const uint32_t sBh = sb + OFF_BH;
        const uint32_t sBl = sb + OFF_BL;

        // software-pipelined k-steps: load ks+1 fragments under ks MMAs
        ld_frags(fr[0], sAh, sAl, sBh, sBl, 0, aoff, boff);
#pragma unroll
        for (int ks = 0; ks < 4; ks++) {
            if (ks < 3)
                ld_frags(fr[(ks + 1) & 1], sAh, sAl, sBh, sBl, (ks + 1) * 32,
                         aoff, boff);
            do_mmas(fr[ks & 1], d);
        }

        stg++; if (stg >= NSTAGE) stg = 0;
    }
}

// ---------------------------------------------------------------------------
// Merged QKV projection GEMM. blockIdx.z in {0,1,2} selects {Q,K,V}.
// z<2: out = bias+hi/lo split, row-major. z=2: transposed [DDIM, NTOK].
// ---------------------------------------------------------------------------
__global__ void __launch_bounds__(NTHREADS)
proj_gemm(const __nv_bfloat16* __restrict__ qh, const __nv_bfloat16* __restrict__ ql,
          const __nv_bfloat16* __restrict__ kh, const __nv_bfloat16* __restrict__ kl,
          const __nv_bfloat16* __restrict__ vh, const __nv_bfloat16* __restrict__ vl,
          const __nv_bfloat16* __restrict__ wqh, const __nv_bfloat16* __restrict__ wql,
          const __nv_bfloat16* __restrict__ wkh, const __nv_bfloat16* __restrict__ wkl,
          const __nv_bfloat16* __restrict__ wvh, const __nv_bfloat16* __restrict__ wvl,
          const float* __restrict__ bq, const float* __restrict__ bk,
          const float* __restrict__ bv,
          __nv_bfloat16* __restrict__ qph, __nv_bfloat16* __restrict__ qpl,
          __nv_bfloat16* __restrict__ kph, __nv_bfloat16* __restrict__ kpl,
          __nv_bfloat16* __restrict__ vpth, __nv_bfloat16* __restrict__ vptl)
{
    extern __shared__ char smem[];
    const uint32_t sbase = smem_u32(smem);
    const int tid = threadIdx.x;
    const int wid = tid >> 5, lane = tid & 31;
    const int wm = wid & 3, wn = wid >> 2;
    const int mBase = blockIdx.y * 128;
    const int nBase = blockIdx.x * 128;
    const int z = blockIdx.z;

    const __nv_bfloat16* Ah = (z == 0) ? qh : (z == 1) ? kh : vh;
    const __nv_bfloat16* Al = (z == 0) ? ql : (z == 1) ? kl : vl;
    const __nv_bfloat16* Bh = (z == 0) ? wqh : (z == 1) ? wkh : wvh;
    const __nv_bfloat16* Bl = (z == 0) ? wql : (z == 1) ? wkl : wvl;
    const float* bias = (z == 0) ? bq : (z == 1) ? bk : bv;
    __nv_bfloat16* Ch = (z == 0) ? qph : (z == 1) ? kph : vpth;
    __nv_bfloat16* Cl = (z == 0) ? qpl : (z == 1) ? kpl : vptl;

    float d[2][4][4];
#pragma unroll
    for (int i = 0; i < 2; i++)
#pragma unroll
        for (int j = 0; j < 4; j++)
#pragma unroll
            for (int e = 0; e < 4; e++) d[i][j][e] = 0.f;

    gemm_mainloop(Ah + (size_t)mBase * IDIM, Al + (size_t)mBase * IDIM,
                  Bh + (size_t)nBase * IDIM, Bl + (size_t)nBase * IDIM,
                  IDIM, IDIM, IDIM, sbase, tid, wm, wn, lane, d);

    const int row0 = mBase + wm * 32 + (lane >> 2);
    const int col0 = nBase + wn * 32 + (lane & 3) * 2;

#pragma unroll
    for (int mf = 0; mf < 2; mf++) {
#pragma unroll
        for (int nf = 0; nf < 4; nf++) {
            const int r = row0 + mf * 16;
            const int c = col0 + nf * 8;
            const float* dd = d[mf][nf];
            const float b0v = bias[c], b1v = bias[c + 1];
#pragma unroll
            for (int h = 0; h < 2; h++) {
                float v0 = dd[h * 2 + 0] + b0v;
                float v1 = dd[h * 2 + 1] + b1v;
                __nv_bfloat16 h0 = __float2bfloat16(v0);
                __nv_bfloat16 h1 = __float2bfloat16(v1);
                __nv_bfloat16 l0 = __float2bfloat16(v0 - __bfloat162float(h0));
                __nv_bfloat16 l1 = __float2bfloat16(v1 - __bfloat162float(h1));
                int rr = r + h * 8;
                if (z != 2) {
                    size_t o = (size_t)rr * DDIM + c;
                    *(__nv_bfloat162*)(Ch + o) = __nv_bfloat162(h0, h1);
                    *(__nv_bfloat162*)(Cl + o) = __nv_bfloat162(l0, l1);
                } else {
                    Ch[(size_t)c * NTOK + rr] = h0;
                    Cl[(size_t)c * NTOK + rr] = l0;
                    Ch[(size_t)(c + 1) * NTOK + rr] = h1;
                    Cl[(size_t)(c + 1) * NTOK + rr] = l1;
                }
            }
        }
    }
}

// ---------------------------------------------------------------------------
// Generic NT GEMM with fp32 output (logits & AV), batched via strides.
// ---------------------------------------------------------------------------
__global__ void __launch_bounds__(NTHREADS)
hmma_gemm_f32(const __nv_bfloat16* __restrict__ Ah, const __nv_bfloat16* __restrict__ Al,
              const __nv_bfloat16* __restrict__ Bh, const __nv_bfloat16* __restrict__ Bl,
              float* __restrict__ Cf,
              int K, int lda, int ldb, int ldc,
              size_t sA, size_t sB, size_t sC)
{
    extern __shared__ char smem[];
    const uint32_t sbase = smem_u32(smem);
    const int tid = threadIdx.x;
    const int wid = tid >> 5, lane = tid & 31;
    const int wm = wid & 3, wn = wid >> 2;
    const int mBase = blockIdx.y * 128;
    const int nBase = blockIdx.x * 128;
    const int z = blockIdx.z;

    float d[2][4][4];
#pragma unroll
    for (int i = 0; i < 2; i++)
#pragma unroll
        for (int j = 0; j < 4; j++)
#pragma unroll
            for (int e = 0; e < 4; e++) d[i][j][e] = 0.f;

    gemm_mainloop(Ah + z * sA + (size_t)mBase * lda, Al + z * sA + (size_t)mBase * lda,
                  Bh + z * sB + (size_t)nBase * ldb, Bl + z * sB + (size_t)nBase * ldb,
                  K, lda, ldb, sbase, tid, wm, wn, lane, d);

    const int row0 = mBase + wm * 32 + (lane >> 2);
    const int col0 = nBase + wn * 32 + (lane & 3) * 2;
    float* Cp = Cf + z * sC;

#pragma unroll
    for (int mf = 0; mf < 2; mf++) {
#pragma unroll
        for (int nf = 0; nf < 4; nf++) {
            const int r = row0 + mf * 16;
            const int c = col0 + nf * 8;
            const float* dd = d[mf][nf];
            *(float2*)(Cp + (size_t)r * ldc + c) = make_float2(dd[0], dd[1]);
            *(float2*)(Cp + (size_t)(r + 8) * ldc + c) = make_float2(dd[2], dd[3]);
        }
    }
}

// ---------------------------------------------------------------------------
// fp32 -> (hi, lo) bf16 split; grid.y selects among 3 tensors
// ---------------------------------------------------------------------------
__global__ void __launch_bounds__(256)
split_f32_3(const float4* __restrict__ x0, __nv_bfloat16* __restrict__ h0p, __nv_bfloat16* __restrict__ l0p,
            const float4* __restrict__ x1, __nv_bfloat16* __restrict__ h1p, __nv_bfloat16* __restrict__ l1p,
            const float4* __restrict__ x2, __nv_bfloat16* __restrict__ h2p, __nv_bfloat16* __restrict__ l2p,
            int n4)
{
    int i = blockIdx.x * 256 + threadIdx.x;
    if (i >= n4) return;
    int s = blockIdx.y;
    const float4* x = (s == 0) ? x0 : (s == 1) ? x1 : x2;
    __nv_bfloat16* hi = (s == 0) ? h0p : (s == 1) ? h1p : h2p;
    __nv_bfloat16* lo = (s == 0) ? l0p : (s == 1) ? l1p : l2p;

    float4 v = x[i];
    float vv[4] = {v.x, v.y, v.z, v.w};
    __nv_bfloat162 h2[2], l2[2];
#pragma unroll
    for (int j = 0; j < 4; j++) {
        __nv_bfloat16 h = __float2bfloat16(vv[j]);
        __nv_bfloat16 l = __float2bfloat16(vv[j] - __bfloat162float(h));
        ((__nv_bfloat16*)h2)[j] = h;
        ((__nv_bfloat16*)l2)[j] = l;
    }
    ((__nv_bfloat162*)hi)[i * 2]     = h2[0];
    ((__nv_bfloat162*)hi)[i * 2 + 1] = h2[1];
    ((__nv_bfloat162*)lo)[i * 2]     = l2[0];
    ((__nv_bfloat162*)lo)[i * 2 + 1] = l2[1];
}

// Merged W[K,N] fp32 -> WT hi/lo [N,K] bf16 for all 3 weights (grid.z)
__global__ void __launch_bounds__(256)
transpose_split_3(const float* __restrict__ W0, __nv_bfloat16* __restrict__ T0h, __nv_bfloat16* __restrict__ T0l,
                  const float* __restrict__ W1, __nv_bfloat16* __restrict__ T1h, __nv_bfloat16* __restrict__ T1l,
                  const float* __restrict__ W2, __nv_bfloat16* __restrict__ T2h, __nv_bfloat16* __restrict__ T2l,
                  int rows, int cols)
{
    __shared__ float tile[32][33];
    int s = blockIdx.z;
    const float* W = (s == 0) ? W0 : (s == 1) ? W1 : W2;
    __nv_bfloat16* Th = (s == 0) ? T0h : (s == 1) ? T1h : T2h;
    __nv_bfloat16* Tl = (s == 0) ? T0l : (s == 1) ? T1l : T2l;

    int bx = blockIdx.x * 32;  // n
    int by = blockIdx.y * 32;  // k
    int tx = threadIdx.x & 31;
    int ty = threadIdx.x >> 5; // 0..7
#pragma unroll
    for (int i = ty; i < 32; i += 8)
        tile[i][tx] = W[(size_t)(by + i) * cols + bx + tx];
    __syncthreads();
#pragma unroll
    for (int i = ty; i < 32; i += 8) {
        float v = tile[tx][i];  // = W[by+tx][bx+i]
        __nv_bfloat16 h = __float2bfloat16(v);
        __nv_bfloat16 l = __float2bfloat16(v - __bfloat162float(h));
        size_t o = (size_t)(bx + i) * rows + by + tx;
        Th[o] = h;
        Tl[o] = l;
    }
}

// ---------------------------------------------------------------------------
// scale+mask+softmax, fp32 logits in -> bf16 hi/lo attn out
// ---------------------------------------------------------------------------
__global__ void __launch_bounds__(256)
softmax_split(const float* __restrict__ logits, const float* __restrict__ mask,
              __nv_bfloat16* __restrict__ ah, __nv_bfloat16* __restrict__ al,
              float scale)
{
    __shared__ float red[8];
    __shared__ float bval;

    size_t row = blockIdx.x;
    int q = (int)(row & (SDIM - 1));
    const float* rp = logits + row * (size_t)SDIM;
    const float* mp = mask + (size_t)q * SDIM;
    int t = threadIdx.x;

    float4 a = ((const float4*)rp)[t];
    float4 b = ((const float4*)rp)[t + 256];
    float4 ma = ((const float4*)mp)[t];
    float4 mb = ((const float4*)mp)[t + 256];
    float x[8];
    x[0] = fmaf(a.x, scale, ma.x); x[1] = fmaf(a.y, scale, ma.y);
    x[2] = fmaf(a.z, scale, ma.z); x[3] = fmaf(a.w, scale, ma.w);
    x[4] = fmaf(b.x, scale, mb.x); x[5] = fmaf(b.y, scale, mb.y);
    x[6] = fmaf(b.z, scale, mb.z); x[7] = fmaf(b.w, scale, mb.w);

    float mx = x[0];
#pragma unroll
    for (int i = 1; i < 8; i++) mx = fmaxf(mx, x[i]);
#pragma unroll
    for (int o = 16; o; o >>= 1) mx = fmaxf(mx, __shfl_xor_sync(0xffffffffu, mx, o));
    if ((t & 31) == 0) red[t >> 5] = mx;
    __syncthreads();
    if (t == 0) {
        float m = red[0];
#pragma unroll
        for (int i = 1; i < 8; i++) m = fmaxf(m, red[i]);
        bval = m;
    }
    __syncthreads();
    mx = bval;

    float s = 0.f;
#pragma unroll
    for (int i = 0; i < 8; i++) { x[i] = __expf(x[i] - mx); s += x[i]; }
#pragma unroll
    for (int o = 16; o; o >>= 1) s += __shfl_xor_sync(0xffffffffu, s, o);
    if ((t & 31) == 0) red[t >> 5] = s;
    __syncthreads();
    if (t == 0) {
        float ss = 0.f;
#pragma unroll
        for (int i = 0; i < 8; i++) ss += red[i];
        bval = 1.f / ss;
    }
    __syncthreads();
    float inv = bval;

    __nv_bfloat162* ah2 = (__nv_bfloat162*)(ah + row * (size_t)SDIM);
    __nv_bfloat162* al2 = (__nv_bfloat162*)(al + row * (size_t)SDIM);
#pragma unroll
    for (int half = 0; half < 2; half++) {
#pragma unroll
        for (int p = 0; p < 2; p++) {
            float p0 = x[half * 4 + p * 2 + 0] * inv;
            float p1 = x[half * 4 + p * 2 + 1] * inv;
            __nv_bfloat16 h0 = __float2bfloat16(p0);
            __nv_bfloat16 h1 = __float2bfloat16(p1);
            __nv_bfloat16 l0 = __float2bfloat16(p0 - __bfloat162float(h0));
            __nv_bfloat16 l1 = __float2bfloat16(p1 - __bfloat162float(h1));
            int idx = half * 512 + t * 2 + p;
            ah2[idx] = __nv_bfloat162(h0, h1);
            al2[idx] = __nv_bfloat162(l0, l1);
        }
    }
}

// ---------------------------------------------------------------------------
extern "C" void kernel_launch(void* const* d_in, const int* in_sizes, int n_in,
                              void* d_out, int out_size)
{
    const float* q    = (const float*)d_in[0];
    const float* k    = (const float*)d_in[1];
    const float* v    = (const float*)d_in[2];
    const float* mask = (const float*)d_in[3];
    const float* wq   = (const float*)d_in[4];
    const float* bq   = (const float*)d_in[5];
    const float* wk   = (const float*)d_in[6];
    const float* bk   = (const float*)d_in[7];
    const float* wv   = (const float*)d_in[8];
    const float* bv   = (const float*)d_in[9];
    float* out = (float*)d_out;

#define SYM(p, s) do { void* _t; cudaGetSymbolAddress(&_t, s); p = (decltype(p))_t; } while (0)
    __nv_bfloat16 *qh, *ql, *kh, *kl, *vh, *vl;
    __nv_bfloat16 *wqth, *wqtl, *wkth, *wktl, *wvth, *wvtl;
    __nv_bfloat16 *qph, *qpl, *kph, *kpl, *vpth, *vptl, *ah, *al;
    float* lg;
    SYM(qh, g_qh); SYM(ql, g_ql); SYM(kh, g_kh); SYM(kl, g_kl);
    SYM(vh, g_vh); SYM(vl, g_vl);
    SYM(wqth, g_wqt_h); SYM(wqtl, g_wqt_l);
    SYM(wkth, g_wkt_h); SYM(wktl, g_wkt_l);
    SYM(wvth, g_wvt_h); SYM(wvtl, g_wvt_l);
    SYM(qph, g_qph); SYM(qpl, g_qpl); SYM(kph, g_kph); SYM(kpl, g_kpl);
    SYM(vpth, g_vpth); SYM(vptl, g_vptl);
    SYM(ah, g_ah); SYM(al, g_al);
    SYM(lg, g_logits);
#undef SYM

    cudaFuncSetAttribute(proj_gemm, cudaFuncAttributeMaxDynamicSharedMemorySize, SMEM_TOTAL);
    cudaFuncSetAttribute(hmma_gemm_f32, cudaFuncAttributeMaxDynamicSharedMemorySize, SMEM_TOTAL);

    const int n4 = NTOK * IDIM / 4;

    // 1: merged hi/lo split of q, k, v
    split_f32_3<<<dim3(n4 / 256, 3), 256>>>((const float4*)q, qh, ql,
                                            (const float4*)k, kh, kl,
                                            (const float4*)v, vh, vl, n4);
    // 2: merged weight transpose+split
    transpose_split_3<<<dim3(IDIM / 32, IDIM / 32, 3), 256>>>(
        wq, wqth, wqtl, wk, wkth, wktl, wv, wvth, wvtl, IDIM, DDIM);

    // 3: merged QKV projections (z selects operand set; z=2 writes vp^T)
    dim3 gp(DDIM / 128, NTOK / 128, 3);
    proj_gemm<<<gp, NTHREADS, SMEM_TOTAL>>>(qh, ql, kh, kl, vh, vl,
                                            wqth, wqtl, wkth, wktl, wvth, wvtl,
                                            bq, bk, bv,
                                            qph, qpl, kph, kpl, vpth, vptl);

    // 4: logits = qp @ kp^T (batched over B)   <- ncu profiles this launch
    dim3 gl(SDIM / 128, SDIM / 128, BDIM);
    hmma_gemm_f32<<<gl, NTHREADS, SMEM_TOTAL>>>(qph, qpl, kph, kpl, lg,
                                                DDIM, DDIM, DDIM, SDIM,
                                                (size_t)SDIM * DDIM, (size_t)SDIM * DDIM,
                                                (size_t)SDIM * SDIM);

    // 5: softmax -> attn hi/lo
    softmax_split<<<BDIM * SDIM, 256>>>(lg, mask, ah, al, 0.03125f);

    // 6: out = attn @ vp (B operand = vp^T, batch offset = column shift)
    dim3 ga(DDIM / 128, SDIM / 128, BDIM);
    hmma_gemm_f32<<<ga, NTHREADS, SMEM_TOTAL>>>(ah, al, vpth, vptl, out,
                                                SDIM, SDIM, NTOK, DDIM,
                                                (size_t)SDIM * SDIM, (size_t)SDIM,
                                                (size_t)SDIM * DDIM);
}

// round 9
// speedup vs baseline: 1.1137x; 1.0115x over previous
#include <cuda_runtime.h>
#include <cuda_bf16.h>
#include <cstdint>

#define BDIM 4
#define SDIM 2048
#define IDIM 1024
#define DDIM 1024
#define NTOK (BDIM * SDIM)   // 8192

// ---------------------------------------------------------------------------
// Device scratch (allocation-free rule)
// ---------------------------------------------------------------------------
__device__ __align__(128) __nv_bfloat16 g_qh[(size_t)NTOK * IDIM];
__device__ __align__(128) __nv_bfloat16 g_ql[(size_t)NTOK * IDIM];
__device__ __align__(128) __nv_bfloat16 g_kh[(size_t)NTOK * IDIM];
__device__ __align__(128) __nv_bfloat16 g_kl[(size_t)NTOK * IDIM];
__device__ __align__(128) __nv_bfloat16 g_vh[(size_t)NTOK * IDIM];
__device__ __align__(128) __nv_bfloat16 g_vl[(size_t)NTOK * IDIM];
__device__ __align__(128) __nv_bfloat16 g_wqt_h[(size_t)DDIM * IDIM];
__device__ __align__(128) __nv_bfloat16 g_wqt_l[(size_t)DDIM * IDIM];
__device__ __align__(128) __nv_bfloat16 g_wkt_h[(size_t)DDIM * IDIM];
__device__ __align__(128) __nv_bfloat16 g_wkt_l[(size_t)DDIM * IDIM];
__device__ __align__(128) __nv_bfloat16 g_wvt_h[(size_t)DDIM * IDIM];
__device__ __align__(128) __nv_bfloat16 g_wvt_l[(size_t)DDIM * IDIM];
__device__ __align__(128) __nv_bfloat16 g_qph[(size_t)NTOK * DDIM];
__device__ __align__(128) __nv_bfloat16 g_qpl[(size_t)NTOK * DDIM];
__device__ __align__(128) __nv_bfloat16 g_kph[(size_t)NTOK * DDIM];
__device__ __align__(128) __nv_bfloat16 g_kpl[(size_t)NTOK * DDIM];
__device__ __align__(128) __nv_bfloat16 g_vpth[(size_t)DDIM * NTOK];  // [D, tokens]
__device__ __align__(128) __nv_bfloat16 g_vptl[(size_t)DDIM * NTOK];
__device__ __align__(128) float g_logits[(size_t)BDIM * SDIM * SDIM];
__device__ __align__(128) __nv_bfloat16 g_ah[(size_t)BDIM * SDIM * SDIM];
__device__ __align__(128) __nv_bfloat16 g_al[(size_t)BDIM * SDIM * SDIM];

// ---------------------------------------------------------------------------
// PTX helpers
// ---------------------------------------------------------------------------
__device__ __forceinline__ uint32_t smem_u32(const void* p) {
    uint32_t a;
    asm("{ .reg .u64 t; cvta.to.shared.u64 t, %1; cvt.u32.u64 %0, t; }"
        : "=r"(a) : "l"(p));
    return a;
}

__device__ __forceinline__ void cp16(uint32_t d, const void* g) {
    asm volatile("cp.async.cg.shared.global [%0], [%1], 16;" :: "r"(d), "l"(g) : "memory");
}
#define CP_COMMIT() asm volatile("cp.async.commit_group;" ::: "memory")
#define CP_WAIT1()  asm volatile("cp.async.wait_group 1;" ::: "memory")

__device__ __forceinline__ void ldsm4(uint32_t* r, uint32_t addr) {
    asm volatile("ldmatrix.sync.aligned.m8n8.x4.shared.b16 {%0,%1,%2,%3}, [%4];"
        : "=r"(r[0]), "=r"(r[1]), "=r"(r[2]), "=r"(r[3]) : "r"(addr));
}

// mma.sync m16n8k16 bf16 -> fp32 accumulate
__device__ __forceinline__ void mma_bf16(float* d, const uint32_t* a,
                                         uint32_t b0, uint32_t b1) {
    asm volatile(
        "mma.sync.aligned.m16n8k16.row.col.f32.bf16.bf16.f32 "
        "{%0,%1,%2,%3}, {%4,%5,%6,%7}, {%8,%9}, {%0,%1,%2,%3};"
        : "+f"(d[0]), "+f"(d[1]), "+f"(d[2]), "+f"(d[3])
        : "r"(a[0]), "r"(a[1]), "r"(a[2]), "r"(a[3]), "r"(b0), "r"(b1));
}

// SMEM stage: 4 arrays of 128 rows x 80B pitch (64B = 32 bf16, K-tile 32)
#define KT 32
#define ROWB 80
#define ARR_BYTES (128 * ROWB)          // 10240
#define OFF_AH 0
#define OFF_AL ARR_BYTES
#define OFF_BH (2 * ARR_BYTES)
#define OFF_BL (3 * ARR_BYTES)
#define STG_BYTES (4 * ARR_BYTES)       // 40960
#define NSTAGE 2
#define SMEM_TOTAL (NSTAGE * STG_BYTES) // 81920 -> 2 CTAs/SM

#define NTHREADS 256

__device__ __forceinline__ void load_arr(const __nv_bfloat16* __restrict__ G,
                                         int ldg, int kt, uint32_t dst, int tid) {
#pragma unroll
    for (int i = 0; i < 2; i++) {
        int idx = tid + i * NTHREADS;
        int row = idx >> 2;
        int c = idx & 3;
        cp16(dst + row * ROWB + c * 16, (const void*)(G + (size_t)row * ldg + kt + c * 8));
    }
}

// ---------------------------------------------------------------------------
// Shared mainloop: D[128,128] += A[128,K] * B[128,K]^T (NT, hi/lo 3-product).
// 8 warps (4 m x 2 n), warp tile 32x64; 2-stage ping-pong, 2 CTAs/SM.
// ---------------------------------------------------------------------------
__device__ __forceinline__ void gemm_mainloop(
    const __nv_bfloat16* __restrict__ Ahb, const __nv_bfloat16* __restrict__ Alb,
    const __nv_bfloat16* __restrict__ Bhb, const __nv_bfloat16* __restrict__ Blb,
    int K, int lda, int ldb,
    uint32_t sbase, int tid, int wm, int wn, int lane,
    float d[2][8][4])
{
    const int w8 = lane & 7, j8 = lane >> 3;
    int aoff[2], boff[4];
#pragma unroll
    for (int mf = 0; mf < 2; mf++)
        aoff[mf] = (wm * 32 + mf * 16 + w8 + 8 * (j8 & 1)) * ROWB + (j8 >> 1) * 16;
#pragma unroll
    for (int g = 0; g < 4; g++)
        boff[g] = (wn * 64 + g * 16 + w8 + 8 * (j8 >> 1)) * ROWB + (j8 & 1) * 16;

    const int T = K / KT;

    // preload stages 0,1
#pragma unroll
    for (int p = 0; p < 2; p++) {
        uint32_t b = sbase + p * STG_BYTES;
        load_arr(Ahb, lda, p * KT, b + OFF_AH, tid);
        load_arr(Alb, lda, p * KT, b + OFF_AL, tid);
        load_arr(Bhb, ldb, p * KT, b + OFF_BH, tid);
        load_arr(Blb, ldb, p * KT, b + OFF_BL, tid);
        CP_COMMIT();
    }

    for (int t = 0; t < T; t++) {
        CP_WAIT1();            // stage t landed
        __syncthreads();

        const uint32_t sb = sbase + (t & 1) * STG_BYTES;
        const uint32_t sAh = sb + OFF_AH;
        const uint32_t sAl = sb + OFF_AL;
        const uint32_t sBh = sb + OFF_BH;
        const uint32_t sBl = sb + OFF_BL;

#pragma unroll
        for (int ks = 0; ks < 2; ks++) {
            const int kb = ks * 32;
            uint32_t ah[2][4], al[2][4];
            ldsm4(ah[0], sAh + aoff[0] + kb);
            ldsm4(ah[1], sAh + aoff[1] + kb);
            ldsm4(al[0], sAl + aoff[0] + kb);
            ldsm4(al[1], sAl + aoff[1] + kb);
#pragma unroll
            for (int g = 0; g < 4; g++) {
                uint32_t bh[4], bl[4];
                ldsm4(bh, sBh + boff[g] + kb);
                ldsm4(bl, sBl + boff[g] + kb);
#pragma unroll
                for (int sub = 0; sub < 2; sub++) {
                    const int nf = g * 2 + sub;
                    const uint32_t bh0 = bh[sub * 2], bh1 = bh[sub * 2 + 1];
                    const uint32_t bl0 = bl[sub * 2], bl1 = bl[sub * 2 + 1];
                    mma_bf16(d[0][nf], ah[0], bh0, bh1);
                    mma_bf16(d[1][nf], ah[1], bh0, bh1);
                    mma_bf16(d[0][nf], ah[0], bl0, bl1);
                    mma_bf16(d[1][nf], ah[1], bl0, bl1);
                    mma_bf16(d[0][nf], al[0], bh0, bh1);
                    mma_bf16(d[1][nf], al[1], bh0, bh1);
                }
            }
        }

        __syncthreads();       // all warps finished reading slot t&1
        if (t + 2 < T) {
            const int kt = (t + 2) * KT;
            load_arr(Ahb, lda, kt, sb + OFF_AH, tid);
            load_arr(Alb, lda, kt, sb + OFF_AL, tid);
            load_arr(Bhb, ldb, kt, sb + OFF_BH, tid);
            load_arr(Blb, ldb, kt, sb + OFF_BL, tid);
        }
        CP_COMMIT();           // always commit to keep group count fixed
    }
}

// ---------------------------------------------------------------------------
// Merged QKV projection GEMM. blockIdx.z in {0,1,2} selects {Q,K,V}.
// z<2: out = bias+hi/lo split, row-major. z=2: transposed [DDIM, NTOK].
// ---------------------------------------------------------------------------
__global__ void __launch_bounds__(NTHREADS, 2)
proj_gemm(const __nv_bfloat16* __restrict__ qh, const __nv_bfloat16* __restrict__ ql,
          const __nv_bfloat16* __restrict__ kh, const __nv_bfloat16* __restrict__ kl,
          const __nv_bfloat16* __restrict__ vh, const __nv_bfloat16* __restrict__ vl,
          const __nv_bfloat16* __restrict__ wqh, const __nv_bfloat16* __restrict__ wql,
          const __nv_bfloat16* __restrict__ wkh, const __nv_bfloat16* __restrict__ wkl,
          const __nv_bfloat16* __restrict__ wvh, const __nv_bfloat16* __restrict__ wvl,
          const float* __restrict__ bq, const float* __restrict__ bk,
          const float* __restrict__ bv,
          __nv_bfloat16* __restrict__ qph, __nv_bfloat16* __restrict__ qpl,
          __nv_bfloat16* __restrict__ kph, __nv_bfloat16* __restrict__ kpl,
          __nv_bfloat16* __restrict__ vpth, __nv_bfloat16* __restrict__ vptl)
{
    extern __shared__ char smem[];
    const uint32_t sbase = smem_u32(smem);
    const int tid = threadIdx.x;
    const int wid = tid >> 5, lane = tid & 31;
    const int wm = wid & 3, wn = wid >> 2;
    const int mBase = blockIdx.y * 128;
    const int nBase = blockIdx.x * 128;
    const int z = blockIdx.z;

    const __nv_bfloat16* Ah = (z == 0) ? qh : (z == 1) ? kh : vh;
    const __nv_bfloat16* Al = (z == 0) ? ql : (z == 1) ? kl : vl;
    const __nv_bfloat16* Bh = (z == 0) ? wqh : (z == 1) ? wkh : wvh;
    const __nv_bfloat16* Bl = (z == 0) ? wql : (z == 1) ? wkl : wvl;
    const float* bias = (z == 0) ? bq : (z == 1) ? bk : bv;
    __nv_bfloat16* Ch = (z == 0) ? qph : (z == 1) ? kph : vpth;
    __nv_bfloat16* Cl = (z == 0) ? qpl : (z == 1) ? kpl : vptl;

    float d[2][8][4];
#pragma unroll
    for (int i = 0; i < 2; i++)
#pragma unroll
        for (int j = 0; j < 8; j++)
#pragma unroll
            for (int e = 0; e < 4; e++) d[i][j][e] = 0.f;

    gemm_mainloop(Ah + (size_t)mBase * IDIM, Al + (size_t)mBase * IDIM,
                  Bh + (size_t)nBase * IDIM, Bl + (size_t)nBase * IDIM,
                  IDIM, IDIM, IDIM, sbase, tid, wm, wn, lane, d);

    const int row0 = mBase + wm * 32 + (lane >> 2);
    const int col0 = nBase + wn * 64 + (lane & 3) * 2;

#pragma unroll
    for (int mf = 0; mf < 2; mf++) {
#pragma unroll
        for (int nf = 0; nf < 8; nf++) {
            const int r = row0 + mf * 16;
            const int c = col0 + nf * 8;
            const float* dd = d[mf][nf];
            const float b0v = bias[c], b1v = bias[c + 1];
#pragma unroll
            for (int h = 0; h < 2; h++) {
                float v0 = dd[h * 2 + 0] + b0v;
                float v1 = dd[h * 2 + 1] + b1v;
                __nv_bfloat16 h0 = __float2bfloat16(v0);
                __nv_bfloat16 h1 = __float2bfloat16(v1);
                __nv_bfloat16 l0 = __float2bfloat16(v0 - __bfloat162float(h0));
                __nv_bfloat16 l1 = __float2bfloat16(v1 - __bfloat162float(h1));
                int rr = r + h * 8;
                if (z != 2) {
                    size_t o = (size_t)rr * DDIM + c;
                    *(__nv_bfloat162*)(Ch + o) = __nv_bfloat162(h0, h1);
                    *(__nv_bfloat162*)(Cl + o) = __nv_bfloat162(l0, l1);
                } else {
                    Ch[(size_t)c * NTOK + rr] = h0;
                    Cl[(size_t)c * NTOK + rr] = l0;
                    Ch[(size_t)(c + 1) * NTOK + rr] = h1;
                    Cl[(size_t)(c + 1) * NTOK + rr] = l1;
                }
            }
        }
    }
}

// ---------------------------------------------------------------------------
// Generic NT GEMM with fp32 output (logits & AV), batched via strides.
// ---------------------------------------------------------------------------
__global__ void __launch_bounds__(NTHREADS, 2)
hmma_gemm_f32(const __nv_bfloat16* __restrict__ Ah, const __nv_bfloat16* __restrict__ Al,
              const __nv_bfloat16* __restrict__ Bh, const __nv_bfloat16* __restrict__ Bl,
              float* __restrict__ Cf,
              int K, int lda, int ldb, int ldc,
              size_t sA, size_t sB, size_t sC)
{
    extern __shared__ char smem[];
    const uint32_t sbase = smem_u32(smem);
    const int tid = threadIdx.x;
    const int wid = tid >> 5, lane = tid & 31;
    const int wm = wid & 3, wn = wid >> 2;
    const int mBase = blockIdx.y * 128;
    const int nBase = blockIdx.x * 128;
    const int z = blockIdx.z;

    float d[2][8][4];
#pragma unroll
    for (int i = 0; i < 2; i++)
#pragma unroll
        for (int j = 0; j < 8; j++)
#pragma unroll
            for (int e = 0; e < 4; e++) d[i][j][e] = 0.f;

    gemm_mainloop(Ah + z * sA + (size_t)mBase * lda, Al + z * sA + (size_t)mBase * lda,
                  Bh + z * sB + (size_t)nBase * ldb, Bl + z * sB + (size_t)nBase * ldb,
                  K, lda, ldb, sbase, tid, wm, wn, lane, d);

    const int row0 = mBase + wm * 32 + (lane >> 2);
    const int col0 = nBase + wn * 64 + (lane & 3) * 2;
    float* Cp = Cf + z * sC;

#pragma unroll
    for (int mf = 0; mf < 2; mf++) {
#pragma unroll
        for (int nf = 0; nf < 8; nf++) {
            const int r = row0 + mf * 16;
            const int c = col0 + nf * 8;
            const float* dd = d[mf][nf];
            *(float2*)(Cp + (size_t)r * ldc + c) = make_float2(dd[0], dd[1]);
            *(float2*)(Cp + (size_t)(r + 8) * ldc + c) = make_float2(dd[2], dd[3]);
        }
    }
}

// ---------------------------------------------------------------------------
// fp32 -> (hi, lo) bf16 split; grid.y selects among 3 tensors
// ---------------------------------------------------------------------------
__global__ void __launch_bounds__(256)
split_f32_3(const float4* __restrict__ x0, __nv_bfloat16* __restrict__ h0p, __nv_bfloat16* __restrict__ l0p,
            const float4* __restrict__ x1, __nv_bfloat16* __restrict__ h1p, __nv_bfloat16* __restrict__ l1p,
            const float4* __restrict__ x2, __nv_bfloat16* __restrict__ h2p, __nv_bfloat16* __restrict__ l2p,
            int n4)
{
    int i = blockIdx.x * 256 + threadIdx.x;
    if (i >= n4) return;
    int s = blockIdx.y;
    const float4* x = (s == 0) ? x0 : (s == 1) ? x1 : x2;
    __nv_bfloat16* hi = (s == 0) ? h0p : (s == 1) ? h1p : h2p;
    __nv_bfloat16* lo = (s == 0) ? l0p : (s == 1) ? l1p : l2p;

    float4 v = x[i];
    float vv[4] = {v.x, v.y, v.z, v.w};
    __nv_bfloat162 h2[2], l2[2];
#pragma unroll
    for (int j = 0; j < 4; j++) {
        __nv_bfloat16 h = __float2bfloat16(vv[j]);
        __nv_bfloat16 l = __float2bfloat16(vv[j] - __bfloat162float(h));
        ((__nv_bfloat16*)h2)[j] = h;
        ((__nv_bfloat16*)l2)[j] = l;
    }
    ((__nv_bfloat162*)hi)[i * 2]     = h2[0];
    ((__nv_bfloat162*)hi)[i * 2 + 1] = h2[1];
    ((__nv_bfloat162*)lo)[i * 2]     = l2[0];
    ((__nv_bfloat162*)lo)[i * 2 + 1] = l2[1];
}

// Merged W[K,N] fp32 -> WT hi/lo [N,K] bf16 for all 3 weights (grid.z)
__global__ void __launch_bounds__(256)
transpose_split_3(const float* __restrict__ W0, __nv_bfloat16* __restrict__ T0h, __nv_bfloat16* __restrict__ T0l,
                  const float* __restrict__ W1, __nv_bfloat16* __restrict__ T1h, __nv_bfloat16* __restrict__ T1l,
                  const float* __restrict__ W2, __nv_bfloat16* __restrict__ T2h, __nv_bfloat16* __restrict__ T2l,
                  int rows, int cols)
{
    __shared__ float tile[32][33];
    int s = blockIdx.z;
    const float* W = (s == 0) ? W0 : (s == 1) ? W1 : W2;
    __nv_bfloat16* Th = (s == 0) ? T0h : (s == 1) ? T1h : T2h;
    __nv_bfloat16* Tl = (s == 0) ? T0l : (s == 1) ? T1l : T2l;

    int bx = blockIdx.x * 32;  // n
    int by = blockIdx.y * 32;  // k
    int tx = threadIdx.x & 31;
    int ty = threadIdx.x >> 5; // 0..7
#pragma unroll
    for (int i = ty; i < 32; i += 8)
        tile[i][tx] = W[(size_t)(by + i) * cols + bx + tx];
    __syncthreads();
#pragma unroll
    for (int i = ty; i < 32; i += 8) {
        float v = tile[tx][i];  // = W[by+tx][bx+i]
        __nv_bfloat16 h = __float2bfloat16(v);
        __nv_bfloat16 l = __float2bfloat16(v - __bfloat162float(h));
        size_t o = (size_t)(bx + i) * rows + by + tx;
        Th[o] = h;
        Tl[o] = l;
    }
}

// ---------------------------------------------------------------------------
// scale+mask+softmax, fp32 logits in -> bf16 hi/lo attn out
// ---------------------------------------------------------------------------
__global__ void __launch_bounds__(256)
softmax_split(const float* __restrict__ logits, const float* __restrict__ mask,
              __nv_bfloat16* __restrict__ ah, __nv_bfloat16* __restrict__ al,
              float scale)
{
    __shared__ float red[8];
    __shared__ float bval;

    size_t row = blockIdx.x;
    int q = (int)(row & (SDIM - 1));
    const float* rp = logits + row * (size_t)SDIM;
    const float* mp = mask + (size_t)q * SDIM;
    int t = threadIdx.x;

    float4 a = ((const float4*)rp)[t];
    float4 b = ((const float4*)rp)[t + 256];
    float4 ma = ((const float4*)mp)[t];
    float4 mb = ((const float4*)mp)[t + 256];
    float x[8];
    x[0] = fmaf(a.x, scale, ma.x); x[1] = fmaf(a.y, scale, ma.y);
    x[2] = fmaf(a.z, scale, ma.z); x[3] = fmaf(a.w, scale, ma.w);
    x[4] = fmaf(b.x, scale, mb.x); x[5] = fmaf(b.y, scale, mb.y);
    x[6] = fmaf(b.z, scale, mb.z); x[7] = fmaf(b.w, scale, mb.w);

    float mx = x[0];
#pragma unroll
    for (int i = 1; i < 8; i++) mx = fmaxf(mx, x[i]);
#pragma unroll
    for (int o = 16; o; o >>= 1) mx = fmaxf(mx, __shfl_xor_sync(0xffffffffu, mx, o));
    if ((t & 31) == 0) red[t >> 5] = mx;
    __syncthreads();
    if (t == 0) {
        float m = red[0];
#pragma unroll
        for (int i = 1; i < 8; i++) m = fmaxf(m, red[i]);
        bval = m;
    }
    __syncthreads();
    mx = bval;

    float s = 0.f;
#pragma unroll
    for (int i = 0; i < 8; i++) { x[i] = __expf(x[i] - mx); s += x[i]; }
#pragma unroll
    for (int o = 16; o; o >>= 1) s += __shfl_xor_sync(0xffffffffu, s, o);
    if ((t & 31) == 0) red[t >> 5] = s;
    __syncthreads();
    if (t == 0) {
        float ss = 0.f;
#pragma unroll
        for (int i = 0; i < 8; i++) ss += red[i];
        bval = 1.f / ss;
    }
    __syncthreads();
    float inv = bval;

    __nv_bfloat162* ah2 = (__nv_bfloat162*)(ah + row * (size_t)SDIM);
    __nv_bfloat162* al2 = (__nv_bfloat162*)(al + row * (size_t)SDIM);
#pragma unroll
    for (int half = 0; half < 2; half++) {
#pragma unroll
        for (int p = 0; p < 2; p++) {
            float p0 = x[half * 4 + p * 2 + 0] * inv;
            float p1 = x[half * 4 + p * 2 + 1] * inv;
            __nv_bfloat16 h0 = __float2bfloat16(p0);
            __nv_bfloat16 h1 = __float2bfloat16(p1);
            __nv_bfloat16 l0 = __float2bfloat16(p0 - __bfloat162float(h0));
            __nv_bfloat16 l1 = __float2bfloat16(p1 - __bfloat162float(h1));
            int idx = half * 512 + t * 2 + p;
            ah2[idx] = __nv_bfloat162(h0, h1);
            al2[idx] = __nv_bfloat162(l0, l1);
        }
    }
}

// ---------------------------------------------------------------------------
extern "C" void kernel_launch(void* const* d_in, const int* in_sizes, int n_in,
                              void* d_out, int out_size)
{
    const float* q    = (const float*)d_in[0];
    const float* k    = (const float*)d_in[1];
    const float* v    = (const float*)d_in[2];
    const float* mask = (const float*)d_in[3];
    const float* wq   = (const float*)d_in[4];
    const float* bq   = (const float*)d_in[5];
    const float* wk   = (const float*)d_in[6];
    const float* bk   = (const float*)d_in[7];
    const float* wv   = (const float*)d_in[8];
    const float* bv   = (const float*)d_in[9];
    float* out = (float*)d_out;

#define SYM(p, s) do { void* _t; cudaGetSymbolAddress(&_t, s); p = (decltype(p))_t; } while (0)
    __nv_bfloat16 *qh, *ql, *kh, *kl, *vh, *vl;
    __nv_bfloat16 *wqth, *wqtl, *wkth, *wktl, *wvth, *wvtl;
    __nv_bfloat16 *qph, *qpl, *kph, *kpl, *vpth, *vptl, *ah, *al;
    float* lg;
    SYM(qh, g_qh); SYM(ql, g_ql); SYM(kh, g_kh); SYM(kl, g_kl);
    SYM(vh, g_vh); SYM(vl, g_vl);
    SYM(wqth, g_wqt_h); SYM(wqtl, g_wqt_l);
    SYM(wkth, g_wkt_h); SYM(wktl, g_wkt_l);
    SYM(wvth, g_wvt_h); SYM(wvtl, g_wvt_l);
    SYM(qph, g_qph); SYM(qpl, g_qpl); SYM(kph, g_kph); SYM(kpl, g_kpl);
    SYM(vpth, g_vpth); SYM(vptl, g_vptl);
    SYM(ah, g_ah); SYM(al, g_al);
    SYM(lg, g_logits);
#undef SYM

    cudaFuncSetAttribute(proj_gemm, cudaFuncAttributeMaxDynamicSharedMemorySize, SMEM_TOTAL);
    cudaFuncSetAttribute(hmma_gemm_f32, cudaFuncAttributeMaxDynamicSharedMemorySize, SMEM_TOTAL);

    const int n4 = NTOK * IDIM / 4;

    // 1: merged hi/lo split of q, k, v
    split_f32_3<<<dim3(n4 / 256, 3), 256>>>((const float4*)q, qh, ql,
                                            (const float4*)k, kh, kl,
                                            (const float4*)v, vh, vl, n4);
    // 2: merged weight transpose+split
    transpose_split_3<<<dim3(IDIM / 32, IDIM / 32, 3), 256>>>(
        wq, wqth, wqtl, wk, wkth, wktl, wv, wvth, wvtl, IDIM, DDIM);

    // 3: merged QKV projections (z selects operand set; z=2 writes vp^T)
    dim3 gp(DDIM / 128, NTOK / 128, 3);
    proj_gemm<<<gp, NTHREADS, SMEM_TOTAL>>>(qh, ql, kh, kl, vh, vl,
                                            wqth, wqtl, wkth, wktl, wvth, wvtl,
                                            bq, bk, bv,
                                            qph, qpl, kph, kpl, vpth, vptl);

    // 4: logits = qp @ kp^T (batched over B)   <- ncu profiles this launch
    dim3 gl(SDIM / 128, SDIM / 128, BDIM);
    hmma_gemm_f32<<<gl, NTHREADS, SMEM_TOTAL>>>(qph, qpl, kph, kpl, lg,
                                                DDIM, DDIM, DDIM, SDIM,
                                                (size_t)SDIM * DDIM, (size_t)SDIM * DDIM,
                                                (size_t)SDIM * SDIM);

    // 5: softmax -> attn hi/lo
    softmax_split<<<BDIM * SDIM, 256>>>(lg, mask, ah, al, 0.03125f);

    // 6: out = attn @ vp (B operand = vp^T, batch offset = column shift)
    dim3 ga(DDIM / 128, SDIM / 128, BDIM);
    hmma_gemm_f32<<<ga, NTHREADS, SMEM_TOTAL>>>(ah, al, vpth, vptl, out,
                                                SDIM, SDIM, NTOK, DDIM,
                                                (size_t)SDIM * SDIM, (size_t)SDIM,
                                                (size_t)SDIM * DDIM);
}